// round 9
// baseline (speedup 1.0000x reference)
#include <cuda_runtime.h>
#include <cuda_fp16.h>
#include <cstdint>
#include <math.h>

// Problem constants
#define Nn   16384
#define Ee   65536
#define Gg   64
#define INF  63
#define K1   64            // layer-1 K padded 63 -> 64
#define HID  2048
#define MIDD 1024
#define NCLS 18
#define SLOPE 0.01f
#define EPS   1e-5f

// ---------------- scratch (device globals; no allocation allowed) ----------------
__device__ __half g_nmh[(size_t)Nn * HID];   // neighbor sum (half2 atomic target) / mean via GEMM
__device__ __half g_xh[(size_t)Nn * HID];    // activations (half)
__device__ __half g_h16[(size_t)Nn * K1];    // padded input features (half)
__device__ float  g_y [(size_t)Nn * HID];    // GEMM output
__device__ float  g_deg[Nn];
__device__ float  g_scale[HID];
__device__ float  g_shift[HID];
__device__ float  g_colsum[HID];
__device__ float  g_colsq[HID];
__device__ float  g_hg[Gg * HID];
__device__ float  g_cnt[Gg];
__device__ float  g_t1[Gg * HID];
__device__ float  g_t2[Gg * MIDD];
// transposed fp16 weights [N=2048 rows, K cols]
__device__ __half g_wh1s[(size_t)HID * K1];
__device__ __half g_wh1n[(size_t)HID * K1];
__device__ __half g_wh2s[(size_t)HID * HID];
__device__ __half g_wh2n[(size_t)HID * HID];
__device__ __half g_wh3s[(size_t)HID * HID];
__device__ __half g_wh3n[(size_t)HID * HID];

// ==================== helpers ====================
__device__ __forceinline__ uint32_t smem_u32(const void* p) {
    uint32_t a;
    asm("{ .reg .u64 t; cvta.to.shared.u64 t, %1; cvt.u32.u64 %0, t; }" : "=r"(a) : "l"(p));
    return a;
}
__device__ __forceinline__ void cp_async16(uint32_t dst, const void* src) {
    asm volatile("cp.async.cg.shared.global [%0], [%1], 16;" :: "r"(dst), "l"(src) : "memory");
}
__device__ __forceinline__ void cp_commit() {
    asm volatile("cp.async.commit_group;" ::: "memory");
}
__device__ __forceinline__ void mma_f16(float* d, const uint32_t* a, const uint32_t* b) {
    asm volatile(
        "mma.sync.aligned.m16n8k16.row.col.f32.f16.f16.f32 "
        "{%0,%1,%2,%3}, {%4,%5,%6,%7}, {%8,%9}, {%0,%1,%2,%3};"
        : "+f"(d[0]), "+f"(d[1]), "+f"(d[2]), "+f"(d[3])
        : "r"(a[0]), "r"(a[1]), "r"(a[2]), "r"(a[3]), "r"(b[0]), "r"(b[1]));
}

// ==================== fp16 mma.sync dual-source GEMM ====================
// Sources ordered NEIGHBOR first, then SELF:
//   acc = (Anb@Bnb^T) * (1/max(deg,1)) [row-wise] + Aself@Bself^T + bias
// Also accumulates per-column sum / sum-of-squares (BN batch stats).
// A [M, K] row-major (stride K), B [2048, K] row-major (stride K), K in {64, 2048}.
#define PADW 36
#define ROWB 144
#define OPB  (128 * ROWB)
#define STAGE_BYTES (2 * OPB)
#define NSTAGE 3
#define TCG_SMEM_BYTES (NSTAGE * STAGE_BYTES)    // 110592 B
#define KCH 64

__device__ __forceinline__ void tcg_issue_chunk(uint32_t sb, int stage, int tid,
                                                const __half* A, const __half* B,
                                                int rowBlk, int colBlk, int k0, int lda) {
    uint32_t base = sb + (uint32_t)stage * STAGE_BYTES;
    #pragma unroll
    for (int i = 0; i < 4; i++) {
        int t = tid + i * 256;
        int r = t >> 3, sg = t & 7;
        uint32_t off = (uint32_t)r * ROWB + (uint32_t)sg * 16;
        cp_async16(base + off, A + (size_t)(rowBlk + r) * lda + k0 + sg * 8);
        cp_async16(base + OPB + off, B + (size_t)(colBlk + r) * lda + k0 + sg * 8);
    }
}

__global__ void __launch_bounds__(256, 2)
tc_gemm_dual(const __half* __restrict__ Anb, const __half* __restrict__ Bnb,
             const __half* __restrict__ Aself, const __half* __restrict__ Bself,
             const float* __restrict__ bias, const float* __restrict__ deg,
             float* __restrict__ C,
             float* __restrict__ colsum, float* __restrict__ colsq, int K) {
    extern __shared__ __align__(16) float smem[];
    uint32_t sb = smem_u32(smem);
    const int tid  = threadIdx.x;
    const int wid  = tid >> 5;
    const int lane = tid & 31;
    const int rowBlk = blockIdx.y * 128;
    const int colBlk = blockIdx.x * 128;
    const int wm = (wid & 1) * 64;
    const int wn = (wid >> 1) * 32;
    const int lr = lane >> 2;
    const int lc = lane & 3;

    float acc[4][4][4];
    #pragma unroll
    for (int i = 0; i < 4; i++)
        #pragma unroll
        for (int j = 0; j < 4; j++)
            #pragma unroll
            for (int k = 0; k < 4; k++) acc[i][j][k] = 0.0f;

    const int NC  = K / KCH;   // chunks per source
    const int TOT = 2 * NC;

    // chunk -> (A, B, k0)
    auto pick = [&](int idx, const __half*& A, const __half*& B, int& k0) {
        if (idx < NC) { A = Anb;   B = Bnb;   k0 = idx * KCH; }
        else          { A = Aself; B = Bself; k0 = (idx - NC) * KCH; }
    };

    {
        const __half *A, *B; int k0;
        pick(0, A, B, k0);
        tcg_issue_chunk(sb, 0, tid, A, B, rowBlk, colBlk, k0, K);
        cp_commit();
        pick(1, A, B, k0);
        tcg_issue_chunk(sb, 1, tid, A, B, rowBlk, colBlk, k0, K);
        cp_commit();
    }

    int sc = 0;
    for (int c = 0; c < TOT; c++) {
        int n2 = c + 2;
        if (n2 < TOT) {
            const __half *A, *B; int k0;
            pick(n2, A, B, k0);
            int ps = sc + 2; if (ps >= NSTAGE) ps -= NSTAGE;
            tcg_issue_chunk(sb, ps, tid, A, B, rowBlk, colBlk, k0, K);
        }
        cp_commit();
        asm volatile("cp.async.wait_group 2;" ::: "memory");
        __syncthreads();

        const uint32_t* As = (const uint32_t*)smem + (size_t)sc * (STAGE_BYTES / 4);
        const uint32_t* Bs = As + OPB / 4;

        #pragma unroll
        for (int kp = 0; kp < KCH; kp += 16) {
            int kw = kp >> 1;
            uint32_t af[4][4], bf[4][2];
            #pragma unroll
            for (int mt = 0; mt < 4; mt++) {
                int r0 = wm + mt * 16 + lr;
                af[mt][0] = As[r0 * PADW + kw + lc];
                af[mt][1] = As[(r0 + 8) * PADW + kw + lc];
                af[mt][2] = As[r0 * PADW + kw + lc + 4];
                af[mt][3] = As[(r0 + 8) * PADW + kw + lc + 4];
            }
            #pragma unroll
            for (int nt = 0; nt < 4; nt++) {
                int n0 = wn + nt * 8 + lr;
                bf[nt][0] = Bs[n0 * PADW + kw + lc];
                bf[nt][1] = Bs[n0 * PADW + kw + lc + 4];
            }
            #pragma unroll
            for (int mt = 0; mt < 4; mt++)
                #pragma unroll
                for (int nt = 0; nt < 4; nt++)
                    mma_f16(acc[mt][nt], af[mt], bf[nt]);
        }
        __syncthreads();

        // end of neighbor source: scale accumulator rows by 1/max(deg,1)
        if (c == NC - 1) {
            #pragma unroll
            for (int mt = 0; mt < 4; mt++) {
                int gr = rowBlk + wm + mt * 16 + lr;
                float i0 = 1.0f / fmaxf(deg[gr], 1.0f);
                float i1 = 1.0f / fmaxf(deg[gr + 8], 1.0f);
                #pragma unroll
                for (int nt = 0; nt < 4; nt++) {
                    acc[mt][nt][0] *= i0; acc[mt][nt][1] *= i0;
                    acc[mt][nt][2] *= i1; acc[mt][nt][3] *= i1;
                }
            }
        }
        sc++; if (sc >= NSTAGE) sc = 0;
    }

    // epilogue: store +bias, and accumulate per-column sum / sumsq
    #pragma unroll
    for (int nt = 0; nt < 4; nt++) {
        int gc = colBlk + wn + nt * 8 + 2 * lc;
        float bv0 = bias[gc], bv1 = bias[gc + 1];
        float s0 = 0.f, s1 = 0.f, q0 = 0.f, q1 = 0.f;
        #pragma unroll
        for (int mt = 0; mt < 4; mt++) {
            int gr = rowBlk + wm + mt * 16 + lr;
            float v00 = acc[mt][nt][0] + bv0;
            float v01 = acc[mt][nt][1] + bv1;
            float v10 = acc[mt][nt][2] + bv0;
            float v11 = acc[mt][nt][3] + bv1;
            *(float2*)&C[(size_t)gr * HID + gc]       = make_float2(v00, v01);
            *(float2*)&C[(size_t)(gr + 8) * HID + gc] = make_float2(v10, v11);
            s0 += v00 + v10;  s1 += v01 + v11;
            q0 += v00 * v00 + v10 * v10;
            q1 += v01 * v01 + v11 * v11;
        }
        #pragma unroll
        for (int st = 4; st <= 16; st <<= 1) {
            s0 += __shfl_xor_sync(0xFFFFFFFF, s0, st);
            s1 += __shfl_xor_sync(0xFFFFFFFF, s1, st);
            q0 += __shfl_xor_sync(0xFFFFFFFF, q0, st);
            q1 += __shfl_xor_sync(0xFFFFFFFF, q1, st);
        }
        if (lr == 0) {
            atomicAdd(&colsum[gc],     s0);
            atomicAdd(&colsum[gc + 1], s1);
            atomicAdd(&colsq[gc],      q0);
            atomicAdd(&colsq[gc + 1],  q1);
        }
    }
}

// colsum/colsq -> scale/shift
__global__ void bn_scale(const float* __restrict__ colsum, const float* __restrict__ colsq,
                         const float* __restrict__ gamma, const float* __restrict__ beta,
                         float* __restrict__ scale, float* __restrict__ shift) {
    int c = blockIdx.x * blockDim.x + threadIdx.x;
    float mu  = colsum[c] / (float)Nn;
    float var = colsq[c] / (float)Nn - mu * mu;
    float sc  = gamma[c] * rsqrtf(var + EPS);
    scale[c] = sc;
    shift[c] = beta[c] - mu * sc;
}

// ==================== weight transposes (+ fp16 convert) ====================
// W [2048, 2048] -> Wt [2048 rows, 2048 cols]
__global__ void transpose_cvt(const float* __restrict__ W, __half* __restrict__ Wt) {
    __shared__ float tile[32][33];
    int n0 = blockIdx.x * 32, k0 = blockIdx.y * 32;
    int tx = threadIdx.x, ty = threadIdx.y;
    #pragma unroll
    for (int j = 0; j < 4; j++)
        tile[ty + j * 8][tx] = W[(size_t)(k0 + ty + j * 8) * HID + (n0 + tx)];
    __syncthreads();
    #pragma unroll
    for (int j = 0; j < 4; j++)
        Wt[(size_t)(n0 + ty + j * 8) * HID + (k0 + tx)] = __float2half_rn(tile[tx][ty + j * 8]);
}

// W1 [63, 2048] -> Wt [2048 rows, 64 cols] (col 63 zero-padded)
__global__ void transpose_cvt1(const float* __restrict__ W, __half* __restrict__ Wt) {
    __shared__ float tile[32][33];
    int n0 = blockIdx.x * 32, k0 = blockIdx.y * 32;
    int tx = threadIdx.x, ty = threadIdx.y;
    #pragma unroll
    for (int j = 0; j < 4; j++) {
        int k = k0 + ty + j * 8;
        tile[ty + j * 8][tx] = (k < INF) ? W[(size_t)k * HID + (n0 + tx)] : 0.0f;
    }
    __syncthreads();
    #pragma unroll
    for (int j = 0; j < 4; j++)
        Wt[(size_t)(n0 + ty + j * 8) * K1 + (k0 + tx)] = __float2half_rn(tile[tx][ty + j * 8]);
}

// h [Nn, 63] fp32 -> h16 [Nn, 64] half (padded)
__global__ void hpad(const float* __restrict__ h, __half* __restrict__ h16) {
    int row = blockIdx.x;
    int c = threadIdx.x;   // 64 threads
    h16[(size_t)row * K1 + c] = (c < INF) ? __float2half_rn(h[(size_t)row * INF + c]) : __half(0);
}

// ==================== graph kernels ====================
__global__ void deg_kernel(const int* __restrict__ dst, float* __restrict__ deg) {
    int i = blockIdx.x * blockDim.x + threadIdx.x;
    if (i < Ee) atomicAdd(&deg[dst[i]], 1.0f);
}

// half2 atomic scatter: out[dst[e], :] += x[src[e], :].  F = halves per row.
__global__ void scatter_add_h2(const __half* __restrict__ xh, const int* __restrict__ src,
                               const int* __restrict__ dst, __half* __restrict__ out, int F) {
    int e = blockIdx.x;
    int f2 = blockIdx.y * blockDim.x + threadIdx.x;
    if (f2 * 2 >= F) return;
    int s = src[e], d = dst[e];
    __half2 v = *((const __half2*)(xh + (size_t)s * F) + f2);
    atomicAdd((__half2*)(out + (size_t)d * F) + f2, v);
}

// BN apply + leaky relu -> half output.  grid: (HID/4/256, Nn)
__global__ void bn_apply_h(const float* __restrict__ X, __half* __restrict__ Yh,
                           const float* __restrict__ scale, const float* __restrict__ shift) {
    int row = blockIdx.y;
    int f4 = blockIdx.x * blockDim.x + threadIdx.x;
    float4 v = *((const float4*)(X + (size_t)row * HID) + f4);
    float4 sc = *((const float4*)scale + f4);
    float4 sh = *((const float4*)shift + f4);
    v.x = v.x * sc.x + sh.x; v.x = (v.x > 0.0f) ? v.x : SLOPE * v.x;
    v.y = v.y * sc.y + sh.y; v.y = (v.y > 0.0f) ? v.y : SLOPE * v.y;
    v.z = v.z * sc.z + sh.z; v.z = (v.z > 0.0f) ? v.z : SLOPE * v.z;
    v.w = v.w * sc.w + sh.w; v.w = (v.w > 0.0f) ? v.w : SLOPE * v.w;
    __half2 h0 = __floats2half2_rn(v.x, v.y);
    __half2 h1 = __floats2half2_rn(v.z, v.w);
    *((__half2*)(Yh + (size_t)row * HID) + f4 * 2)     = h0;
    *((__half2*)(Yh + (size_t)row * HID) + f4 * 2 + 1) = h1;
}

// layer-3: BN apply + leaky relu + pooled atomic accumulate
__global__ void bn_apply_pool(const float* __restrict__ X, const int* __restrict__ gid,
                              const float* __restrict__ scale, const float* __restrict__ shift,
                              float* __restrict__ hg) {
    int row = blockIdx.y;
    int f4 = blockIdx.x * blockDim.x + threadIdx.x;
    float4 v = *((const float4*)(X + (size_t)row * HID) + f4);
    float4 sc = *((const float4*)scale + f4);
    float4 sh = *((const float4*)shift + f4);
    v.x = v.x * sc.x + sh.x; v.x = (v.x > 0.0f) ? v.x : SLOPE * v.x;
    v.y = v.y * sc.y + sh.y; v.y = (v.y > 0.0f) ? v.y : SLOPE * v.y;
    v.z = v.z * sc.z + sh.z; v.z = (v.z > 0.0f) ? v.z : SLOPE * v.z;
    v.w = v.w * sc.w + sh.w; v.w = (v.w > 0.0f) ? v.w : SLOPE * v.w;
    int g = gid[row];
    float* dst = hg + (size_t)g * HID + f4 * 4;
    atomicAdd(dst,     v.x);
    atomicAdd(dst + 1, v.y);
    atomicAdd(dst + 2, v.z);
    atomicAdd(dst + 3, v.w);
}

// ---------------- pooling tail ----------------
__global__ void cnt_kernel(const int* __restrict__ gid, float* __restrict__ cnt) {
    int i = blockIdx.x * blockDim.x + threadIdx.x;
    if (i < Nn) atomicAdd(&cnt[gid[i]], 1.0f);
}

__global__ void hg_div(float* __restrict__ hg, const float* __restrict__ cnt, int C) {
    int g = blockIdx.y;
    int c = blockIdx.x * blockDim.x + threadIdx.x;
    if (c >= C) return;
    hg[(size_t)g * C + c] *= 1.0f / fmaxf(cnt[g], 1.0f);
}

// ---------------- small MLP head GEMM ----------------
__global__ void head_gemm(const float* __restrict__ X, const float* __restrict__ W,
                          const float* __restrict__ b, float* __restrict__ Y,
                          int K, int Nc, int do_lrelu) {
    extern __shared__ float xs[];
    int r = blockIdx.y;
    for (int i = threadIdx.x; i < K; i += blockDim.x) xs[i] = X[(size_t)r * K + i];
    __syncthreads();
    int c = blockIdx.x * blockDim.x + threadIdx.x;
    if (c >= Nc) return;
    float acc = 0.0f;
    int k = 0;
    for (; k + 4 <= K; k += 4) {
        acc += xs[k    ] * W[(size_t)(k    ) * Nc + c];
        acc += xs[k + 1] * W[(size_t)(k + 1) * Nc + c];
        acc += xs[k + 2] * W[(size_t)(k + 2) * Nc + c];
        acc += xs[k + 3] * W[(size_t)(k + 3) * Nc + c];
    }
    for (; k < K; k++) acc += xs[k] * W[(size_t)k * Nc + c];
    acc += b[c];
    if (do_lrelu) acc = (acc > 0.0f) ? acc : SLOPE * acc;
    Y[(size_t)r * Nc + c] = acc;
}

// ==================== launch ====================
extern "C" void kernel_launch(void* const* d_in, const int* in_sizes, int n_in,
                              void* d_out, int out_size) {
    (void)in_sizes; (void)n_in; (void)out_size;
    const float* h     = (const float*)d_in[0];
    const int*   src   = (const int*)  d_in[1];
    const int*   dst   = (const int*)  d_in[2];
    const int*   gid   = (const int*)  d_in[3];
    const float* Ws1   = (const float*)d_in[4];
    const float* Wn1   = (const float*)d_in[5];
    const float* b1    = (const float*)d_in[6];
    const float* Ws2   = (const float*)d_in[7];
    const float* Wn2   = (const float*)d_in[8];
    const float* b2    = (const float*)d_in[9];
    const float* Ws3   = (const float*)d_in[10];
    const float* Wn3   = (const float*)d_in[11];
    const float* b3    = (const float*)d_in[12];
    const float* g1    = (const float*)d_in[13];
    const float* be1   = (const float*)d_in[14];
    const float* g2    = (const float*)d_in[15];
    const float* be2   = (const float*)d_in[16];
    const float* g3    = (const float*)d_in[17];
    const float* be3   = (const float*)d_in[18];
    const float* fc1_w = (const float*)d_in[19];
    const float* fc1_b = (const float*)d_in[20];
    const float* fc2_w = (const float*)d_in[21];
    const float* fc2_b = (const float*)d_in[22];
    const float* fc3_w = (const float*)d_in[23];
    const float* fc3_b = (const float*)d_in[24];
    float* out = (float*)d_out;

    float *y, *deg, *scale, *shift, *colsum, *colsq, *hg, *cnt, *t1, *t2;
    __half *nmh, *xh, *h16, *wh1s, *wh1n, *wh2s, *wh2n, *wh3s, *wh3n;
    cudaGetSymbolAddress((void**)&nmh,    g_nmh);
    cudaGetSymbolAddress((void**)&xh,     g_xh);
    cudaGetSymbolAddress((void**)&h16,    g_h16);
    cudaGetSymbolAddress((void**)&y,      g_y);
    cudaGetSymbolAddress((void**)&deg,    g_deg);
    cudaGetSymbolAddress((void**)&scale,  g_scale);
    cudaGetSymbolAddress((void**)&shift,  g_shift);
    cudaGetSymbolAddress((void**)&colsum, g_colsum);
    cudaGetSymbolAddress((void**)&colsq,  g_colsq);
    cudaGetSymbolAddress((void**)&hg,     g_hg);
    cudaGetSymbolAddress((void**)&cnt,    g_cnt);
    cudaGetSymbolAddress((void**)&t1,     g_t1);
    cudaGetSymbolAddress((void**)&t2,     g_t2);
    cudaGetSymbolAddress((void**)&wh1s,   g_wh1s);
    cudaGetSymbolAddress((void**)&wh1n,   g_wh1n);
    cudaGetSymbolAddress((void**)&wh2s,   g_wh2s);
    cudaGetSymbolAddress((void**)&wh2n,   g_wh2n);
    cudaGetSymbolAddress((void**)&wh3s,   g_wh3s);
    cudaGetSymbolAddress((void**)&wh3n,   g_wh3n);

    cudaFuncSetAttribute(tc_gemm_dual, cudaFuncAttributeMaxDynamicSharedMemorySize, TCG_SMEM_BYTES);

    cudaStream_t s = 0;

    // weight transposes (+ fp16 convert), input pad
    dim3 tgrid(HID / 32, HID / 32), tblk(32, 8);
    transpose_cvt1<<<dim3(HID / 32, K1 / 32), tblk, 0, s>>>(Ws1, wh1s);
    transpose_cvt1<<<dim3(HID / 32, K1 / 32), tblk, 0, s>>>(Wn1, wh1n);
    transpose_cvt<<<tgrid, tblk, 0, s>>>(Ws2, wh2s);
    transpose_cvt<<<tgrid, tblk, 0, s>>>(Wn2, wh2n);
    transpose_cvt<<<tgrid, tblk, 0, s>>>(Ws3, wh3s);
    transpose_cvt<<<tgrid, tblk, 0, s>>>(Wn3, wh3n);
    hpad<<<Nn, K1, 0, s>>>(h, h16);

    // degrees
    cudaMemsetAsync(deg, 0, Nn * sizeof(float), s);
    deg_kernel<<<Ee / 256, 256, 0, s>>>(dst, deg);

    dim3 tc_grid(HID / 128, Nn / 128);
    dim3 ew4_grid(HID / 4 / 256, Nn);

    // ---- Layer 1 (K = 64, fp16 tensor GEMM, fused BN stats) ----
    cudaMemsetAsync(nmh, 0, (size_t)Nn * K1 * sizeof(__half), s);
    scatter_add_h2<<<dim3(Ee, 1), 32, 0, s>>>(h16, src, dst, nmh, K1);
    cudaMemsetAsync(colsum, 0, HID * sizeof(float), s);
    cudaMemsetAsync(colsq,  0, HID * sizeof(float), s);
    tc_gemm_dual<<<tc_grid, 256, TCG_SMEM_BYTES, s>>>(nmh, wh1n, h16, wh1s, b1, deg, y,
                                                      colsum, colsq, K1);
    bn_scale<<<HID / 256, 256, 0, s>>>(colsum, colsq, g1, be1, scale, shift);
    bn_apply_h<<<ew4_grid, 256, 0, s>>>(y, xh, scale, shift);

    // ---- Layer 2 (fp16 tensor GEMM, fused BN stats + deg-fold) ----
    cudaMemsetAsync(nmh, 0, (size_t)Nn * HID * sizeof(__half), s);
    scatter_add_h2<<<dim3(Ee, HID / 2 / 128), 128, 0, s>>>(xh, src, dst, nmh, HID);
    cudaMemsetAsync(colsum, 0, HID * sizeof(float), s);
    cudaMemsetAsync(colsq,  0, HID * sizeof(float), s);
    tc_gemm_dual<<<tc_grid, 256, TCG_SMEM_BYTES, s>>>(nmh, wh2n, xh, wh2s, b2, deg, y,
                                                      colsum, colsq, HID);
    bn_scale<<<HID / 256, 256, 0, s>>>(colsum, colsq, g2, be2, scale, shift);
    bn_apply_h<<<ew4_grid, 256, 0, s>>>(y, xh, scale, shift);

    // ---- Layer 3 (fp16 tensor GEMM, fused BN stats + deg-fold + fused pooling) ----
    cudaMemsetAsync(nmh, 0, (size_t)Nn * HID * sizeof(__half), s);
    scatter_add_h2<<<dim3(Ee, HID / 2 / 128), 128, 0, s>>>(xh, src, dst, nmh, HID);
    cudaMemsetAsync(colsum, 0, HID * sizeof(float), s);
    cudaMemsetAsync(colsq,  0, HID * sizeof(float), s);
    tc_gemm_dual<<<tc_grid, 256, TCG_SMEM_BYTES, s>>>(nmh, wh3n, xh, wh3s, b3, deg, y,
                                                      colsum, colsq, HID);
    bn_scale<<<HID / 256, 256, 0, s>>>(colsum, colsq, g3, be3, scale, shift);

    cudaMemsetAsync(hg, 0, Gg * HID * sizeof(float), s);
    cudaMemsetAsync(cnt, 0, Gg * sizeof(float), s);
    cnt_kernel<<<Nn / 256, 256, 0, s>>>(gid, cnt);
    bn_apply_pool<<<ew4_grid, 256, 0, s>>>(y, gid, scale, shift, hg);
    hg_div<<<dim3(HID / 256, Gg), 256, 0, s>>>(hg, cnt, HID);

    // ---- MLP head ----
    head_gemm<<<dim3((HID + 127) / 128, Gg), 128, HID * sizeof(float), s>>>(
        hg, fc1_w, fc1_b, t1, HID, HID, 1);
    head_gemm<<<dim3((MIDD + 127) / 128, Gg), 128, HID * sizeof(float), s>>>(
        t1, fc2_w, fc2_b, t2, HID, MIDD, 1);
    head_gemm<<<dim3(1, Gg), 128, MIDD * sizeof(float), s>>>(
        t2, fc3_w, fc3_b, out, MIDD, NCLS, 0);
}

// round 10
// speedup vs baseline: 1.4294x; 1.4294x over previous
#include <cuda_runtime.h>
#include <cuda_fp16.h>
#include <cstdint>
#include <math.h>

// Problem constants
#define Nn   16384
#define Ee   65536
#define Gg   64
#define INF  63
#define K1   64            // layer-1 K padded 63 -> 64
#define HID  2048
#define MIDD 1024
#define NCLS 18
#define SLOPE 0.01f
#define EPS   1e-5f

// ---------------- scratch (device globals; no allocation allowed) ----------------
__device__ __half g_nmh[(size_t)Nn * HID];   // neighbor sum (half2 atomic target)
__device__ __half g_xh[(size_t)Nn * HID];    // activations (half)
__device__ __half g_h16[(size_t)Nn * K1];    // padded input features (half)
__device__ float  g_y [(size_t)Nn * HID];    // GEMM output
__device__ float  g_deg[Nn];
__device__ float  g_scale[HID];
__device__ float  g_shift[HID];
__device__ float  g_colsum[HID];
__device__ float  g_colsq[HID];
__device__ float  g_hg[Gg * HID];
__device__ float  g_cnt[Gg];
__device__ float  g_t1[Gg * HID];
__device__ float  g_t2[Gg * MIDD];
// transposed fp16 weights [N=2048 rows, K cols]
__device__ __half g_wh1s[(size_t)HID * K1];
__device__ __half g_wh1n[(size_t)HID * K1];
__device__ __half g_wh2s[(size_t)HID * HID];
__device__ __half g_wh2n[(size_t)HID * HID];
__device__ __half g_wh3s[(size_t)HID * HID];
__device__ __half g_wh3n[(size_t)HID * HID];

// ==================== helpers ====================
__device__ __forceinline__ uint32_t smem_u32(const void* p) {
    uint32_t a;
    asm("{ .reg .u64 t; cvta.to.shared.u64 t, %1; cvt.u32.u64 %0, t; }" : "=r"(a) : "l"(p));
    return a;
}
__device__ __forceinline__ void cp_async16(uint32_t dst, const void* src) {
    asm volatile("cp.async.cg.shared.global [%0], [%1], 16;" :: "r"(dst), "l"(src) : "memory");
}
__device__ __forceinline__ void cp_commit() {
    asm volatile("cp.async.commit_group;" ::: "memory");
}
__device__ __forceinline__ void mma_f16(float* d, const uint32_t* a, const uint32_t* b) {
    asm volatile(
        "mma.sync.aligned.m16n8k16.row.col.f32.f16.f16.f32 "
        "{%0,%1,%2,%3}, {%4,%5,%6,%7}, {%8,%9}, {%0,%1,%2,%3};"
        : "+f"(d[0]), "+f"(d[1]), "+f"(d[2]), "+f"(d[3])
        : "r"(a[0]), "r"(a[1]), "r"(a[2]), "r"(a[3]), "r"(b[0]), "r"(b[1]));
}

// ==================== fp16 mma.sync dual-source GEMM (compile-time K) ====================
// acc = (Anb@Bnb^T) * (1/max(deg,1)) [row-wise] + Aself@Bself^T + bias
// Also accumulates per-column sum / sum-of-squares (BN batch stats).
#define PADW 36
#define ROWB 144
#define OPB  (128 * ROWB)
#define STAGE_BYTES (2 * OPB)
#define NSTAGE 3
#define TCG_SMEM_BYTES (NSTAGE * STAGE_BYTES)    // 110592 B
#define KCH 64

template<int K>
__device__ __forceinline__ void tcg_issue_chunk(uint32_t sb, int stage, int tid,
                                                const __half* A, const __half* B,
                                                int rowBlk, int colBlk, int k0) {
    uint32_t base = sb + (uint32_t)stage * STAGE_BYTES;
    #pragma unroll
    for (int i = 0; i < 4; i++) {
        int t = tid + i * 256;
        int r = t >> 3, sg = t & 7;
        uint32_t off = (uint32_t)r * ROWB + (uint32_t)sg * 16;
        cp_async16(base + off, A + (size_t)(rowBlk + r) * K + k0 + sg * 8);
        cp_async16(base + OPB + off, B + (size_t)(colBlk + r) * K + k0 + sg * 8);
    }
}

template<int K>
__global__ void __launch_bounds__(256, 2)
tc_gemm_dual(const __half* __restrict__ Anb, const __half* __restrict__ Bnb,
             const __half* __restrict__ Aself, const __half* __restrict__ Bself,
             const float* __restrict__ bias, const float* __restrict__ deg,
             float* __restrict__ C,
             float* __restrict__ colsum, float* __restrict__ colsq) {
    extern __shared__ __align__(16) float smem[];
    uint32_t sb = smem_u32(smem);
    const int tid  = threadIdx.x;
    const int wid  = tid >> 5;
    const int lane = tid & 31;
    const int rowBlk = blockIdx.y * 128;
    const int colBlk = blockIdx.x * 128;
    const int wm = (wid & 1) * 64;
    const int wn = (wid >> 1) * 32;
    const int lr = lane >> 2;
    const int lc = lane & 3;

    float acc[4][4][4];
    #pragma unroll
    for (int i = 0; i < 4; i++)
        #pragma unroll
        for (int j = 0; j < 4; j++)
            #pragma unroll
            for (int k = 0; k < 4; k++) acc[i][j][k] = 0.0f;

    constexpr int NC  = K / KCH;   // chunks per source (compile-time)
    constexpr int TOT = 2 * NC;

    // neighbor source occupies chunks [0, NC), self occupies [NC, TOT)
    tcg_issue_chunk<K>(sb, 0, tid, Anb, Bnb, rowBlk, colBlk, 0);
    cp_commit();
    {
        const __half* A = (1 < NC) ? Anb : Aself;
        const __half* B = (1 < NC) ? Bnb : Bself;
        int k0 = (1 < NC) ? KCH : 0;
        tcg_issue_chunk<K>(sb, 1, tid, A, B, rowBlk, colBlk, k0);
        cp_commit();
    }

    int sc = 0;
    for (int c = 0; c < TOT; c++) {
        int n2 = c + 2;
        if (n2 < TOT) {
            const __half* A = (n2 < NC) ? Anb : Aself;
            const __half* B = (n2 < NC) ? Bnb : Bself;
            int k0 = (n2 & (NC - 1)) * KCH;
            int ps = sc + 2; if (ps >= NSTAGE) ps -= NSTAGE;
            tcg_issue_chunk<K>(sb, ps, tid, A, B, rowBlk, colBlk, k0);
        }
        cp_commit();
        asm volatile("cp.async.wait_group 2;" ::: "memory");
        __syncthreads();

        const uint32_t* As = (const uint32_t*)smem + (size_t)sc * (STAGE_BYTES / 4);
        const uint32_t* Bs = As + OPB / 4;

        #pragma unroll
        for (int kp = 0; kp < KCH; kp += 16) {
            int kw = kp >> 1;
            uint32_t af[4][4], bf[4][2];
            #pragma unroll
            for (int mt = 0; mt < 4; mt++) {
                int r0 = wm + mt * 16 + lr;
                af[mt][0] = As[r0 * PADW + kw + lc];
                af[mt][1] = As[(r0 + 8) * PADW + kw + lc];
                af[mt][2] = As[r0 * PADW + kw + lc + 4];
                af[mt][3] = As[(r0 + 8) * PADW + kw + lc + 4];
            }
            #pragma unroll
            for (int nt = 0; nt < 4; nt++) {
                int n0 = wn + nt * 8 + lr;
                bf[nt][0] = Bs[n0 * PADW + kw + lc];
                bf[nt][1] = Bs[n0 * PADW + kw + lc + 4];
            }
            #pragma unroll
            for (int mt = 0; mt < 4; mt++)
                #pragma unroll
                for (int nt = 0; nt < 4; nt++)
                    mma_f16(acc[mt][nt], af[mt], bf[nt]);
        }
        __syncthreads();

        // end of neighbor source: scale accumulator rows by 1/max(deg,1)
        if (c == NC - 1) {
            #pragma unroll
            for (int mt = 0; mt < 4; mt++) {
                int gr = rowBlk + wm + mt * 16 + lr;
                float i0 = 1.0f / fmaxf(deg[gr], 1.0f);
                float i1 = 1.0f / fmaxf(deg[gr + 8], 1.0f);
                #pragma unroll
                for (int nt = 0; nt < 4; nt++) {
                    acc[mt][nt][0] *= i0; acc[mt][nt][1] *= i0;
                    acc[mt][nt][2] *= i1; acc[mt][nt][3] *= i1;
                }
            }
        }
        sc++; if (sc >= NSTAGE) sc = 0;
    }

    // epilogue: store +bias, accumulate per-column sum / sumsq
    #pragma unroll
    for (int nt = 0; nt < 4; nt++) {
        int gc = colBlk + wn + nt * 8 + 2 * lc;
        float bv0 = bias[gc], bv1 = bias[gc + 1];
        float s0 = 0.f, s1 = 0.f, q0 = 0.f, q1 = 0.f;
        #pragma unroll
        for (int mt = 0; mt < 4; mt++) {
            int gr = rowBlk + wm + mt * 16 + lr;
            float v00 = acc[mt][nt][0] + bv0;
            float v01 = acc[mt][nt][1] + bv1;
            float v10 = acc[mt][nt][2] + bv0;
            float v11 = acc[mt][nt][3] + bv1;
            *(float2*)&C[(size_t)gr * HID + gc]       = make_float2(v00, v01);
            *(float2*)&C[(size_t)(gr + 8) * HID + gc] = make_float2(v10, v11);
            s0 += v00 + v10;  s1 += v01 + v11;
            q0 += v00 * v00 + v10 * v10;
            q1 += v01 * v01 + v11 * v11;
        }
        #pragma unroll
        for (int st = 4; st <= 16; st <<= 1) {
            s0 += __shfl_xor_sync(0xFFFFFFFF, s0, st);
            s1 += __shfl_xor_sync(0xFFFFFFFF, s1, st);
            q0 += __shfl_xor_sync(0xFFFFFFFF, q0, st);
            q1 += __shfl_xor_sync(0xFFFFFFFF, q1, st);
        }
        if (lr == 0) {
            atomicAdd(&colsum[gc],     s0);
            atomicAdd(&colsum[gc + 1], s1);
            atomicAdd(&colsq[gc],      q0);
            atomicAdd(&colsq[gc + 1],  q1);
        }
    }
}

// colsum/colsq -> scale/shift
__global__ void bn_scale(const float* __restrict__ colsum, const float* __restrict__ colsq,
                         const float* __restrict__ gamma, const float* __restrict__ beta,
                         float* __restrict__ scale, float* __restrict__ shift) {
    int c = blockIdx.x * blockDim.x + threadIdx.x;
    float mu  = colsum[c] / (float)Nn;
    float var = colsq[c] / (float)Nn - mu * mu;
    float sc  = gamma[c] * rsqrtf(var + EPS);
    scale[c] = sc;
    shift[c] = beta[c] - mu * sc;
}

// ==================== weight transposes (+ fp16 convert) ====================
__global__ void transpose_cvt(const float* __restrict__ W, __half* __restrict__ Wt) {
    __shared__ float tile[32][33];
    int n0 = blockIdx.x * 32, k0 = blockIdx.y * 32;
    int tx = threadIdx.x, ty = threadIdx.y;
    #pragma unroll
    for (int j = 0; j < 4; j++)
        tile[ty + j * 8][tx] = W[(size_t)(k0 + ty + j * 8) * HID + (n0 + tx)];
    __syncthreads();
    #pragma unroll
    for (int j = 0; j < 4; j++)
        Wt[(size_t)(n0 + ty + j * 8) * HID + (k0 + tx)] = __float2half_rn(tile[tx][ty + j * 8]);
}

// W1 [63, 2048] -> Wt [2048 rows, 64 cols] (col 63 zero-padded)
__global__ void transpose_cvt1(const float* __restrict__ W, __half* __restrict__ Wt) {
    __shared__ float tile[32][33];
    int n0 = blockIdx.x * 32, k0 = blockIdx.y * 32;
    int tx = threadIdx.x, ty = threadIdx.y;
    #pragma unroll
    for (int j = 0; j < 4; j++) {
        int k = k0 + ty + j * 8;
        tile[ty + j * 8][tx] = (k < INF) ? W[(size_t)k * HID + (n0 + tx)] : 0.0f;
    }
    __syncthreads();
    #pragma unroll
    for (int j = 0; j < 4; j++)
        Wt[(size_t)(n0 + ty + j * 8) * K1 + (k0 + tx)] = __float2half_rn(tile[tx][ty + j * 8]);
}

// h [Nn, 63] fp32 -> h16 [Nn, 64] half (padded)
__global__ void hpad(const float* __restrict__ h, __half* __restrict__ h16) {
    int row = blockIdx.x;
    int c = threadIdx.x;   // 64 threads
    h16[(size_t)row * K1 + c] = (c < INF) ? __float2half_rn(h[(size_t)row * INF + c]) : __half(0);
}

// ==================== graph kernels ====================
__global__ void deg_kernel(const int* __restrict__ dst, float* __restrict__ deg) {
    int i = blockIdx.x * blockDim.x + threadIdx.x;
    if (i < Ee) atomicAdd(&deg[dst[i]], 1.0f);
}

// half2 atomic scatter: out[dst[e], :] += x[src[e], :].  F = halves per row.
__global__ void scatter_add_h2(const __half* __restrict__ xh, const int* __restrict__ src,
                               const int* __restrict__ dst, __half* __restrict__ out, int F) {
    int e = blockIdx.x;
    int f2 = blockIdx.y * blockDim.x + threadIdx.x;
    if (f2 * 2 >= F) return;
    int s = src[e], d = dst[e];
    __half2 v = *((const __half2*)(xh + (size_t)s * F) + f2);
    atomicAdd((__half2*)(out + (size_t)d * F) + f2, v);
}

// BN apply + leaky relu -> half output.  grid: (HID/4/256, Nn)
__global__ void bn_apply_h(const float* __restrict__ X, __half* __restrict__ Yh,
                           const float* __restrict__ scale, const float* __restrict__ shift) {
    int row = blockIdx.y;
    int f4 = blockIdx.x * blockDim.x + threadIdx.x;
    float4 v = *((const float4*)(X + (size_t)row * HID) + f4);
    float4 sc = *((const float4*)scale + f4);
    float4 sh = *((const float4*)shift + f4);
    v.x = v.x * sc.x + sh.x; v.x = (v.x > 0.0f) ? v.x : SLOPE * v.x;
    v.y = v.y * sc.y + sh.y; v.y = (v.y > 0.0f) ? v.y : SLOPE * v.y;
    v.z = v.z * sc.z + sh.z; v.z = (v.z > 0.0f) ? v.z : SLOPE * v.z;
    v.w = v.w * sc.w + sh.w; v.w = (v.w > 0.0f) ? v.w : SLOPE * v.w;
    __half2 h0 = __floats2half2_rn(v.x, v.y);
    __half2 h1 = __floats2half2_rn(v.z, v.w);
    *((__half2*)(Yh + (size_t)row * HID) + f4 * 2)     = h0;
    *((__half2*)(Yh + (size_t)row * HID) + f4 * 2 + 1) = h1;
}

// layer-3: BN apply + leaky relu + pooled atomic accumulate
__global__ void bn_apply_pool(const float* __restrict__ X, const int* __restrict__ gid,
                              const float* __restrict__ scale, const float* __restrict__ shift,
                              float* __restrict__ hg) {
    int row = blockIdx.y;
    int f4 = blockIdx.x * blockDim.x + threadIdx.x;
    float4 v = *((const float4*)(X + (size_t)row * HID) + f4);
    float4 sc = *((const float4*)scale + f4);
    float4 sh = *((const float4*)shift + f4);
    v.x = v.x * sc.x + sh.x; v.x = (v.x > 0.0f) ? v.x : SLOPE * v.x;
    v.y = v.y * sc.y + sh.y; v.y = (v.y > 0.0f) ? v.y : SLOPE * v.y;
    v.z = v.z * sc.z + sh.z; v.z = (v.z > 0.0f) ? v.z : SLOPE * v.z;
    v.w = v.w * sc.w + sh.w; v.w = (v.w > 0.0f) ? v.w : SLOPE * v.w;
    int g = gid[row];
    float* dst = hg + (size_t)g * HID + f4 * 4;
    atomicAdd(dst,     v.x);
    atomicAdd(dst + 1, v.y);
    atomicAdd(dst + 2, v.z);
    atomicAdd(dst + 3, v.w);
}

// ---------------- pooling tail ----------------
__global__ void cnt_kernel(const int* __restrict__ gid, float* __restrict__ cnt) {
    int i = blockIdx.x * blockDim.x + threadIdx.x;
    if (i < Nn) atomicAdd(&cnt[gid[i]], 1.0f);
}

__global__ void hg_div(float* __restrict__ hg, const float* __restrict__ cnt, int C) {
    int g = blockIdx.y;
    int c = blockIdx.x * blockDim.x + threadIdx.x;
    if (c >= C) return;
    hg[(size_t)g * C + c] *= 1.0f / fmaxf(cnt[g], 1.0f);
}

// ---------------- small MLP head GEMM ----------------
__global__ void head_gemm(const float* __restrict__ X, const float* __restrict__ W,
                          const float* __restrict__ b, float* __restrict__ Y,
                          int K, int Nc, int do_lrelu) {
    extern __shared__ float xs[];
    int r = blockIdx.y;
    for (int i = threadIdx.x; i < K; i += blockDim.x) xs[i] = X[(size_t)r * K + i];
    __syncthreads();
    int c = blockIdx.x * blockDim.x + threadIdx.x;
    if (c >= Nc) return;
    float acc = 0.0f;
    int k = 0;
    for (; k + 4 <= K; k += 4) {
        acc += xs[k    ] * W[(size_t)(k    ) * Nc + c];
        acc += xs[k + 1] * W[(size_t)(k + 1) * Nc + c];
        acc += xs[k + 2] * W[(size_t)(k + 2) * Nc + c];
        acc += xs[k + 3] * W[(size_t)(k + 3) * Nc + c];
    }
    for (; k < K; k++) acc += xs[k] * W[(size_t)k * Nc + c];
    acc += b[c];
    if (do_lrelu) acc = (acc > 0.0f) ? acc : SLOPE * acc;
    Y[(size_t)r * Nc + c] = acc;
}

// ==================== launch ====================
extern "C" void kernel_launch(void* const* d_in, const int* in_sizes, int n_in,
                              void* d_out, int out_size) {
    (void)in_sizes; (void)n_in; (void)out_size;
    const float* h     = (const float*)d_in[0];
    const int*   src   = (const int*)  d_in[1];
    const int*   dst   = (const int*)  d_in[2];
    const int*   gid   = (const int*)  d_in[3];
    const float* Ws1   = (const float*)d_in[4];
    const float* Wn1   = (const float*)d_in[5];
    const float* b1    = (const float*)d_in[6];
    const float* Ws2   = (const float*)d_in[7];
    const float* Wn2   = (const float*)d_in[8];
    const float* b2    = (const float*)d_in[9];
    const float* Ws3   = (const float*)d_in[10];
    const float* Wn3   = (const float*)d_in[11];
    const float* b3    = (const float*)d_in[12];
    const float* g1    = (const float*)d_in[13];
    const float* be1   = (const float*)d_in[14];
    const float* g2    = (const float*)d_in[15];
    const float* be2   = (const float*)d_in[16];
    const float* g3    = (const float*)d_in[17];
    const float* be3   = (const float*)d_in[18];
    const float* fc1_w = (const float*)d_in[19];
    const float* fc1_b = (const float*)d_in[20];
    const float* fc2_w = (const float*)d_in[21];
    const float* fc2_b = (const float*)d_in[22];
    const float* fc3_w = (const float*)d_in[23];
    const float* fc3_b = (const float*)d_in[24];
    float* out = (float*)d_out;

    float *y, *deg, *scale, *shift, *colsum, *colsq, *hg, *cnt, *t1, *t2;
    __half *nmh, *xh, *h16, *wh1s, *wh1n, *wh2s, *wh2n, *wh3s, *wh3n;
    cudaGetSymbolAddress((void**)&nmh,    g_nmh);
    cudaGetSymbolAddress((void**)&xh,     g_xh);
    cudaGetSymbolAddress((void**)&h16,    g_h16);
    cudaGetSymbolAddress((void**)&y,      g_y);
    cudaGetSymbolAddress((void**)&deg,    g_deg);
    cudaGetSymbolAddress((void**)&scale,  g_scale);
    cudaGetSymbolAddress((void**)&shift,  g_shift);
    cudaGetSymbolAddress((void**)&colsum, g_colsum);
    cudaGetSymbolAddress((void**)&colsq,  g_colsq);
    cudaGetSymbolAddress((void**)&hg,     g_hg);
    cudaGetSymbolAddress((void**)&cnt,    g_cnt);
    cudaGetSymbolAddress((void**)&t1,     g_t1);
    cudaGetSymbolAddress((void**)&t2,     g_t2);
    cudaGetSymbolAddress((void**)&wh1s,   g_wh1s);
    cudaGetSymbolAddress((void**)&wh1n,   g_wh1n);
    cudaGetSymbolAddress((void**)&wh2s,   g_wh2s);
    cudaGetSymbolAddress((void**)&wh2n,   g_wh2n);
    cudaGetSymbolAddress((void**)&wh3s,   g_wh3s);
    cudaGetSymbolAddress((void**)&wh3n,   g_wh3n);

    cudaFuncSetAttribute(tc_gemm_dual<K1>,  cudaFuncAttributeMaxDynamicSharedMemorySize, TCG_SMEM_BYTES);
    cudaFuncSetAttribute(tc_gemm_dual<HID>, cudaFuncAttributeMaxDynamicSharedMemorySize, TCG_SMEM_BYTES);

    cudaStream_t s = 0;

    // weight transposes (+ fp16 convert), input pad
    dim3 tgrid(HID / 32, HID / 32), tblk(32, 8);
    transpose_cvt1<<<dim3(HID / 32, K1 / 32), tblk, 0, s>>>(Ws1, wh1s);
    transpose_cvt1<<<dim3(HID / 32, K1 / 32), tblk, 0, s>>>(Wn1, wh1n);
    transpose_cvt<<<tgrid, tblk, 0, s>>>(Ws2, wh2s);
    transpose_cvt<<<tgrid, tblk, 0, s>>>(Wn2, wh2n);
    transpose_cvt<<<tgrid, tblk, 0, s>>>(Ws3, wh3s);
    transpose_cvt<<<tgrid, tblk, 0, s>>>(Wn3, wh3n);
    hpad<<<Nn, K1, 0, s>>>(h, h16);

    // degrees
    cudaMemsetAsync(deg, 0, Nn * sizeof(float), s);
    deg_kernel<<<Ee / 256, 256, 0, s>>>(dst, deg);

    dim3 tc_grid(HID / 128, Nn / 128);
    dim3 ew4_grid(HID / 4 / 256, Nn);

    // ---- Layer 1 (K = 64, fp16 tensor GEMM, fused BN stats + deg-fold) ----
    cudaMemsetAsync(nmh, 0, (size_t)Nn * K1 * sizeof(__half), s);
    scatter_add_h2<<<dim3(Ee, 1), 32, 0, s>>>(h16, src, dst, nmh, K1);
    cudaMemsetAsync(colsum, 0, HID * sizeof(float), s);
    cudaMemsetAsync(colsq,  0, HID * sizeof(float), s);
    tc_gemm_dual<K1><<<tc_grid, 256, TCG_SMEM_BYTES, s>>>(nmh, wh1n, h16, wh1s, b1, deg, y,
                                                          colsum, colsq);
    bn_scale<<<HID / 256, 256, 0, s>>>(colsum, colsq, g1, be1, scale, shift);
    bn_apply_h<<<ew4_grid, 256, 0, s>>>(y, xh, scale, shift);

    // ---- Layer 2 (fp16 tensor GEMM, fused BN stats + deg-fold) ----
    cudaMemsetAsync(nmh, 0, (size_t)Nn * HID * sizeof(__half), s);
    scatter_add_h2<<<dim3(Ee, HID / 2 / 128), 128, 0, s>>>(xh, src, dst, nmh, HID);
    cudaMemsetAsync(colsum, 0, HID * sizeof(float), s);
    cudaMemsetAsync(colsq,  0, HID * sizeof(float), s);
    tc_gemm_dual<HID><<<tc_grid, 256, TCG_SMEM_BYTES, s>>>(nmh, wh2n, xh, wh2s, b2, deg, y,
                                                           colsum, colsq);
    bn_scale<<<HID / 256, 256, 0, s>>>(colsum, colsq, g2, be2, scale, shift);
    bn_apply_h<<<ew4_grid, 256, 0, s>>>(y, xh, scale, shift);

    // ---- Layer 3 (fp16 tensor GEMM, fused BN stats + deg-fold + fused pooling) ----
    cudaMemsetAsync(nmh, 0, (size_t)Nn * HID * sizeof(__half), s);
    scatter_add_h2<<<dim3(Ee, HID / 2 / 128), 128, 0, s>>>(xh, src, dst, nmh, HID);
    cudaMemsetAsync(colsum, 0, HID * sizeof(float), s);
    cudaMemsetAsync(colsq,  0, HID * sizeof(float), s);
    tc_gemm_dual<HID><<<tc_grid, 256, TCG_SMEM_BYTES, s>>>(nmh, wh3n, xh, wh3s, b3, deg, y,
                                                           colsum, colsq);
    bn_scale<<<HID / 256, 256, 0, s>>>(colsum, colsq, g3, be3, scale, shift);

    cudaMemsetAsync(hg, 0, Gg * HID * sizeof(float), s);
    cudaMemsetAsync(cnt, 0, Gg * sizeof(float), s);
    cnt_kernel<<<Nn / 256, 256, 0, s>>>(gid, cnt);
    bn_apply_pool<<<ew4_grid, 256, 0, s>>>(y, gid, scale, shift, hg);
    hg_div<<<dim3(HID / 256, Gg), 256, 0, s>>>(hg, cnt, HID);

    // ---- MLP head ----
    head_gemm<<<dim3((HID + 127) / 128, Gg), 128, HID * sizeof(float), s>>>(
        hg, fc1_w, fc1_b, t1, HID, HID, 1);
    head_gemm<<<dim3((MIDD + 127) / 128, Gg), 128, HID * sizeof(float), s>>>(
        t1, fc2_w, fc2_b, t2, HID, MIDD, 1);
    head_gemm<<<dim3(1, Gg), 128, MIDD * sizeof(float), s>>>(
        t2, fc3_w, fc3_b, out, MIDD, NCLS, 0);
}

// round 12
// speedup vs baseline: 1.5280x; 1.0690x over previous
#include <cuda_runtime.h>
#include <cuda_fp16.h>
#include <cstdint>
#include <math.h>

// Problem constants
#define Nn   16384
#define Ee   65536
#define Gg   64
#define INF  63
#define K1   64            // layer-1 K padded 63 -> 64
#define HID  2048
#define MIDD 1024
#define NCLS 18
#define SLOPE 0.01f
#define EPS   1e-5f

// ---------------- scratch (device globals; no allocation allowed) ----------------
__device__ __half g_nmh[(size_t)Nn * HID];   // neighbor sum (half2 atomic target)
__device__ __half g_xh[(size_t)Nn * HID];    // activations (half)
__device__ __half g_h16[(size_t)Nn * K1];    // padded input features (half)
__device__ __half g_yh[(size_t)Nn * HID];    // GEMM output (half)
__device__ float  g_deg[Nn];
__device__ float  g_scale[HID];
__device__ float  g_shift[HID];
__device__ float  g_colsum[HID];
__device__ float  g_colsq[HID];
__device__ float  g_hg[Gg * HID];
__device__ float  g_cnt[Gg];
__device__ __half g_hgh[128 * HID];          // padded pooled features (half, rows 64-127 zero)
__device__ __half g_t1h[128 * HID];
__device__ __half g_t2h[128 * MIDD];
// transposed fp16 weights [N rows, K cols]
__device__ __half g_wh1s[(size_t)HID * K1];
__device__ __half g_wh1n[(size_t)HID * K1];
__device__ __half g_wh2s[(size_t)HID * HID];
__device__ __half g_wh2n[(size_t)HID * HID];
__device__ __half g_wh3s[(size_t)HID * HID];
__device__ __half g_wh3n[(size_t)HID * HID];
__device__ __half g_wfc1[(size_t)HID * HID];   // [N=2048, K=2048]
__device__ __half g_wfc2[(size_t)MIDD * HID];  // [N=1024, K=2048]

// ==================== helpers ====================
__device__ __forceinline__ uint32_t smem_u32(const void* p) {
    uint32_t a;
    asm("{ .reg .u64 t; cvta.to.shared.u64 t, %1; cvt.u32.u64 %0, t; }" : "=r"(a) : "l"(p));
    return a;
}
__device__ __forceinline__ void cp_async16(uint32_t dst, const void* src) {
    asm volatile("cp.async.cg.shared.global [%0], [%1], 16;" :: "r"(dst), "l"(src) : "memory");
}
__device__ __forceinline__ void cp_commit() {
    asm volatile("cp.async.commit_group;" ::: "memory");
}
__device__ __forceinline__ void mma_f16(float* d, const uint32_t* a, const uint32_t* b) {
    asm volatile(
        "mma.sync.aligned.m16n8k16.row.col.f32.f16.f16.f32 "
        "{%0,%1,%2,%3}, {%4,%5,%6,%7}, {%8,%9}, {%0,%1,%2,%3};"
        : "+f"(d[0]), "+f"(d[1]), "+f"(d[2]), "+f"(d[3])
        : "r"(a[0]), "r"(a[1]), "r"(a[2]), "r"(a[3]), "r"(b[0]), "r"(b[1]));
}

// ==================== fp16 mma.sync GEMM (compile-time K / C-stride / modes) ====================
// DUAL:  acc = (Anb@Bnb^T) * (1/max(deg,1)) [row-wise] + Aself@Bself^T + bias
// !DUAL: acc = Aself@Bself^T + bias
// HEAD:  epilogue = lrelu, no BN stats.   !HEAD: epilogue = BN column sum/sumsq.
// Output C is fp16, row stride CS.
#define PADW 36
#define ROWB 144
#define OPB  (128 * ROWB)
#define STAGE_BYTES (2 * OPB)
#define NSTAGE 3
#define TCG_SMEM_BYTES (NSTAGE * STAGE_BYTES)    // 110592 B
#define KCH 64

template<int K>
__device__ __forceinline__ void tcg_issue_chunk(uint32_t sb, int stage, int tid,
                                                const __half* A, const __half* B,
                                                int rowBlk, int colBlk, int k0) {
    uint32_t base = sb + (uint32_t)stage * STAGE_BYTES;
    #pragma unroll
    for (int i = 0; i < 4; i++) {
        int t = tid + i * 256;
        int r = t >> 3, sg = t & 7;
        uint32_t off = (uint32_t)r * ROWB + (uint32_t)sg * 16;
        cp_async16(base + off, A + (size_t)(rowBlk + r) * K + k0 + sg * 8);
        cp_async16(base + OPB + off, B + (size_t)(colBlk + r) * K + k0 + sg * 8);
    }
}

template<int K, int CS, bool DUAL, bool HEAD>
__global__ void __launch_bounds__(256, 2)
tc_gemm(const __half* __restrict__ Anb, const __half* __restrict__ Bnb,
        const __half* __restrict__ Aself, const __half* __restrict__ Bself,
        const float* __restrict__ bias, const float* __restrict__ deg,
        __half* __restrict__ C,
        float* __restrict__ colsum, float* __restrict__ colsq) {
    extern __shared__ __align__(16) float smem[];
    uint32_t sb = smem_u32(smem);
    const int tid  = threadIdx.x;
    const int wid  = tid >> 5;
    const int lane = tid & 31;
    const int rowBlk = blockIdx.y * 128;
    const int colBlk = blockIdx.x * 128;
    const int wm = (wid & 1) * 64;
    const int wn = (wid >> 1) * 32;
    const int lr = lane >> 2;
    const int lc = lane & 3;

    float acc[4][4][4];
    #pragma unroll
    for (int i = 0; i < 4; i++)
        #pragma unroll
        for (int j = 0; j < 4; j++)
            #pragma unroll
            for (int k = 0; k < 4; k++) acc[i][j][k] = 0.0f;

    constexpr int NC  = K / KCH;
    constexpr int TOT = DUAL ? 2 * NC : NC;

    // chunk idx < NC -> first source (neighbor if DUAL else self)
    {
        const __half* A0 = DUAL ? Anb : Aself;
        const __half* B0 = DUAL ? Bnb : Bself;
        tcg_issue_chunk<K>(sb, 0, tid, A0, B0, rowBlk, colBlk, 0);
        cp_commit();
        if (TOT > 1) {
            const __half* A = (DUAL && 1 >= NC) ? Aself : A0;
            const __half* B = (DUAL && 1 >= NC) ? Bself : B0;
            int k0 = (1 & (NC - 1)) * KCH;
            tcg_issue_chunk<K>(sb, 1, tid, A, B, rowBlk, colBlk, k0);
        }
        cp_commit();
    }

    int sc = 0;
    for (int c = 0; c < TOT; c++) {
        int n2 = c + 2;
        if (n2 < TOT) {
            const __half* A = (!DUAL || n2 >= NC) ? Aself : Anb;
            const __half* B = (!DUAL || n2 >= NC) ? Bself : Bnb;
            int k0 = (n2 & (NC - 1)) * KCH;
            int ps = sc + 2; if (ps >= NSTAGE) ps -= NSTAGE;
            tcg_issue_chunk<K>(sb, ps, tid, A, B, rowBlk, colBlk, k0);
        }
        cp_commit();
        asm volatile("cp.async.wait_group 2;" ::: "memory");
        __syncthreads();

        const uint32_t* As = (const uint32_t*)smem + (size_t)sc * (STAGE_BYTES / 4);
        const uint32_t* Bs = As + OPB / 4;

        #pragma unroll
        for (int kp = 0; kp < KCH; kp += 16) {
            int kw = kp >> 1;
            uint32_t af[4][4], bf[4][2];
            #pragma unroll
            for (int mt = 0; mt < 4; mt++) {
                int r0 = wm + mt * 16 + lr;
                af[mt][0] = As[r0 * PADW + kw + lc];
                af[mt][1] = As[(r0 + 8) * PADW + kw + lc];
                af[mt][2] = As[r0 * PADW + kw + lc + 4];
                af[mt][3] = As[(r0 + 8) * PADW + kw + lc + 4];
            }
            #pragma unroll
            for (int nt = 0; nt < 4; nt++) {
                int n0 = wn + nt * 8 + lr;
                bf[nt][0] = Bs[n0 * PADW + kw + lc];
                bf[nt][1] = Bs[n0 * PADW + kw + lc + 4];
            }
            #pragma unroll
            for (int mt = 0; mt < 4; mt++)
                #pragma unroll
                for (int nt = 0; nt < 4; nt++)
                    mma_f16(acc[mt][nt], af[mt], bf[nt]);
        }
        __syncthreads();

        if (DUAL && c == NC - 1) {
            #pragma unroll
            for (int mt = 0; mt < 4; mt++) {
                int gr = rowBlk + wm + mt * 16 + lr;
                float i0 = 1.0f / fmaxf(deg[gr], 1.0f);
                float i1 = 1.0f / fmaxf(deg[gr + 8], 1.0f);
                #pragma unroll
                for (int nt = 0; nt < 4; nt++) {
                    acc[mt][nt][0] *= i0; acc[mt][nt][1] *= i0;
                    acc[mt][nt][2] *= i1; acc[mt][nt][3] *= i1;
                }
            }
        }
        sc++; if (sc >= NSTAGE) sc = 0;
    }

    // epilogue
    #pragma unroll
    for (int nt = 0; nt < 4; nt++) {
        int gc = colBlk + wn + nt * 8 + 2 * lc;
        float bv0 = bias[gc], bv1 = bias[gc + 1];
        float s0 = 0.f, s1 = 0.f, q0 = 0.f, q1 = 0.f;
        #pragma unroll
        for (int mt = 0; mt < 4; mt++) {
            int gr = rowBlk + wm + mt * 16 + lr;
            float v00 = acc[mt][nt][0] + bv0;
            float v01 = acc[mt][nt][1] + bv1;
            float v10 = acc[mt][nt][2] + bv0;
            float v11 = acc[mt][nt][3] + bv1;
            if (HEAD) {
                v00 = (v00 > 0.f) ? v00 : SLOPE * v00;
                v01 = (v01 > 0.f) ? v01 : SLOPE * v01;
                v10 = (v10 > 0.f) ? v10 : SLOPE * v10;
                v11 = (v11 > 0.f) ? v11 : SLOPE * v11;
            }
            *(__half2*)&C[(size_t)gr * CS + gc]       = __floats2half2_rn(v00, v01);
            *(__half2*)&C[(size_t)(gr + 8) * CS + gc] = __floats2half2_rn(v10, v11);
            if (!HEAD) {
                s0 += v00 + v10;  s1 += v01 + v11;
                q0 += v00 * v00 + v10 * v10;
                q1 += v01 * v01 + v11 * v11;
            }
        }
        if (!HEAD) {
            #pragma unroll
            for (int st = 4; st <= 16; st <<= 1) {
                s0 += __shfl_xor_sync(0xFFFFFFFF, s0, st);
                s1 += __shfl_xor_sync(0xFFFFFFFF, s1, st);
                q0 += __shfl_xor_sync(0xFFFFFFFF, q0, st);
                q1 += __shfl_xor_sync(0xFFFFFFFF, q1, st);
            }
            if (lr == 0) {
                atomicAdd(&colsum[gc],     s0);
                atomicAdd(&colsum[gc + 1], s1);
                atomicAdd(&colsq[gc],      q0);
                atomicAdd(&colsq[gc + 1],  q1);
            }
        }
    }
}

// colsum/colsq -> scale/shift
__global__ void bn_scale(const float* __restrict__ colsum, const float* __restrict__ colsq,
                         const float* __restrict__ gamma, const float* __restrict__ beta,
                         float* __restrict__ scale, float* __restrict__ shift) {
    int c = blockIdx.x * blockDim.x + threadIdx.x;
    float mu  = colsum[c] / (float)Nn;
    float var = colsq[c] / (float)Nn - mu * mu;
    float sc  = gamma[c] * rsqrtf(var + EPS);
    scale[c] = sc;
    shift[c] = beta[c] - mu * sc;
}

// ==================== weight transposes (+ fp16 convert) ====================
// generic: W [Kd, Nd] row-major -> Wt [Nd, Kd] half.  grid (Nd/32, Kd/32), block (32,8)
__global__ void transpose_cvt_g(const float* __restrict__ W, __half* __restrict__ Wt,
                                int Kd, int Nd) {
    __shared__ float tile[32][33];
    int n0 = blockIdx.x * 32, k0 = blockIdx.y * 32;
    int tx = threadIdx.x, ty = threadIdx.y;
    #pragma unroll
    for (int j = 0; j < 4; j++)
        tile[ty + j * 8][tx] = W[(size_t)(k0 + ty + j * 8) * Nd + (n0 + tx)];
    __syncthreads();
    #pragma unroll
    for (int j = 0; j < 4; j++)
        Wt[(size_t)(n0 + ty + j * 8) * Kd + (k0 + tx)] = __float2half_rn(tile[tx][ty + j * 8]);
}

// W1 [63, 2048] -> Wt [2048 rows, 64 cols] (col 63 zero-padded)
__global__ void transpose_cvt1(const float* __restrict__ W, __half* __restrict__ Wt) {
    __shared__ float tile[32][33];
    int n0 = blockIdx.x * 32, k0 = blockIdx.y * 32;
    int tx = threadIdx.x, ty = threadIdx.y;
    #pragma unroll
    for (int j = 0; j < 4; j++) {
        int k = k0 + ty + j * 8;
        tile[ty + j * 8][tx] = (k < INF) ? W[(size_t)k * HID + (n0 + tx)] : 0.0f;
    }
    __syncthreads();
    #pragma unroll
    for (int j = 0; j < 4; j++)
        Wt[(size_t)(n0 + ty + j * 8) * K1 + (k0 + tx)] = __float2half_rn(tile[tx][ty + j * 8]);
}

// h [Nn, 63] fp32 -> h16 [Nn, 64] half (padded)
__global__ void hpad(const float* __restrict__ h, __half* __restrict__ h16) {
    int row = blockIdx.x;
    int c = threadIdx.x;
    h16[(size_t)row * K1 + c] = (c < INF) ? __float2half_rn(h[(size_t)row * INF + c]) : __half(0);
}

// ==================== graph kernels ====================
__global__ void deg_kernel(const int* __restrict__ dst, float* __restrict__ deg) {
    int i = blockIdx.x * blockDim.x + threadIdx.x;
    if (i < Ee) atomicAdd(&deg[dst[i]], 1.0f);
}

// half2 atomic scatter: out[dst[e], :] += x[src[e], :]
__global__ void scatter_add_h2(const __half* __restrict__ xh, const int* __restrict__ src,
                               const int* __restrict__ dst, __half* __restrict__ out, int F) {
    int e = blockIdx.x;
    int f2 = blockIdx.y * blockDim.x + threadIdx.x;
    if (f2 * 2 >= F) return;
    int s = src[e], d = dst[e];
    __half2 v = *((const __half2*)(xh + (size_t)s * F) + f2);
    atomicAdd((__half2*)(out + (size_t)d * F) + f2, v);
}

// BN apply + leaky relu: half in (y), half out (x).  grid: (HID/4/256, Nn)
__global__ void bn_apply_h(const __half* __restrict__ Y, __half* __restrict__ Xh,
                           const float* __restrict__ scale, const float* __restrict__ shift) {
    int row = blockIdx.y;
    int f4 = blockIdx.x * blockDim.x + threadIdx.x;
    const __half2* yp = (const __half2*)(Y + (size_t)row * HID) + f4 * 2;
    float2 a = __half22float2(yp[0]);
    float2 b = __half22float2(yp[1]);
    float4 sc = *((const float4*)scale + f4);
    float4 sh = *((const float4*)shift + f4);
    float vx = a.x * sc.x + sh.x; vx = (vx > 0.f) ? vx : SLOPE * vx;
    float vy = a.y * sc.y + sh.y; vy = (vy > 0.f) ? vy : SLOPE * vy;
    float vz = b.x * sc.z + sh.z; vz = (vz > 0.f) ? vz : SLOPE * vz;
    float vw = b.y * sc.w + sh.w; vw = (vw > 0.f) ? vw : SLOPE * vw;
    __half2* xp = (__half2*)(Xh + (size_t)row * HID) + f4 * 2;
    xp[0] = __floats2half2_rn(vx, vy);
    xp[1] = __floats2half2_rn(vz, vw);
}

// layer-3: BN apply + leaky relu + pooled atomic accumulate (half in)
__global__ void bn_apply_pool(const __half* __restrict__ Y, const int* __restrict__ gid,
                              const float* __restrict__ scale, const float* __restrict__ shift,
                              float* __restrict__ hg) {
    int row = blockIdx.y;
    int f4 = blockIdx.x * blockDim.x + threadIdx.x;
    const __half2* yp = (const __half2*)(Y + (size_t)row * HID) + f4 * 2;
    float2 a = __half22float2(yp[0]);
    float2 b = __half22float2(yp[1]);
    float4 sc = *((const float4*)scale + f4);
    float4 sh = *((const float4*)shift + f4);
    float vx = a.x * sc.x + sh.x; vx = (vx > 0.f) ? vx : SLOPE * vx;
    float vy = a.y * sc.y + sh.y; vy = (vy > 0.f) ? vy : SLOPE * vy;
    float vz = b.x * sc.z + sh.z; vz = (vz > 0.f) ? vz : SLOPE * vz;
    float vw = b.y * sc.w + sh.w; vw = (vw > 0.f) ? vw : SLOPE * vw;
    int g = gid[row];
    float* dst = hg + (size_t)g * HID + f4 * 4;
    atomicAdd(dst,     vx);
    atomicAdd(dst + 1, vy);
    atomicAdd(dst + 2, vz);
    atomicAdd(dst + 3, vw);
}

// ---------------- pooling tail ----------------
__global__ void cnt_kernel(const int* __restrict__ gid, float* __restrict__ cnt) {
    int i = blockIdx.x * blockDim.x + threadIdx.x;
    if (i < Nn) atomicAdd(&cnt[gid[i]], 1.0f);
}

// divide + convert to padded half matrix (rows 64-127 already zero)
__global__ void hg_div_h(const float* __restrict__ hg, const float* __restrict__ cnt,
                         __half* __restrict__ hgh) {
    int g = blockIdx.y;
    int c = blockIdx.x * blockDim.x + threadIdx.x;
    float inv = 1.0f / fmaxf(cnt[g], 1.0f);
    hgh[(size_t)g * HID + c] = __float2half_rn(hg[(size_t)g * HID + c] * inv);
}

// ---------------- tiny final GEMM (fc3), half input ----------------
__global__ void head_gemm_h(const __half* __restrict__ X, const float* __restrict__ W,
                            const float* __restrict__ b, float* __restrict__ Y,
                            int K, int Nc) {
    extern __shared__ float xs[];
    int r = blockIdx.y;
    for (int i = threadIdx.x; i < K; i += blockDim.x) xs[i] = __half2float(X[(size_t)r * K + i]);
    __syncthreads();
    int c = blockIdx.x * blockDim.x + threadIdx.x;
    if (c >= Nc) return;
    float acc = 0.0f;
    for (int k = 0; k < K; k++) acc += xs[k] * W[(size_t)k * Nc + c];
    Y[(size_t)r * Nc + c] = acc + b[c];
}

// ==================== launch ====================
extern "C" void kernel_launch(void* const* d_in, const int* in_sizes, int n_in,
                              void* d_out, int out_size) {
    (void)in_sizes; (void)n_in; (void)out_size;
    const float* h     = (const float*)d_in[0];
    const int*   src   = (const int*)  d_in[1];
    const int*   dst   = (const int*)  d_in[2];
    const int*   gid   = (const int*)  d_in[3];
    const float* Ws1   = (const float*)d_in[4];
    const float* Wn1   = (const float*)d_in[5];
    const float* b1    = (const float*)d_in[6];
    const float* Ws2   = (const float*)d_in[7];
    const float* Wn2   = (const float*)d_in[8];
    const float* b2    = (const float*)d_in[9];
    const float* Ws3   = (const float*)d_in[10];
    const float* Wn3   = (const float*)d_in[11];
    const float* b3    = (const float*)d_in[12];
    const float* g1    = (const float*)d_in[13];
    const float* be1   = (const float*)d_in[14];
    const float* g2    = (const float*)d_in[15];
    const float* be2   = (const float*)d_in[16];
    const float* g3    = (const float*)d_in[17];
    const float* be3   = (const float*)d_in[18];
    const float* fc1_w = (const float*)d_in[19];
    const float* fc1_b = (const float*)d_in[20];
    const float* fc2_w = (const float*)d_in[21];
    const float* fc2_b = (const float*)d_in[22];
    const float* fc3_w = (const float*)d_in[23];
    const float* fc3_b = (const float*)d_in[24];
    float* out = (float*)d_out;

    float *deg, *scale, *shift, *colsum, *colsq, *hg, *cnt;
    __half *nmh, *xh, *h16, *yh, *hgh, *t1h, *t2h;
    __half *wh1s, *wh1n, *wh2s, *wh2n, *wh3s, *wh3n, *wfc1, *wfc2;
    cudaGetSymbolAddress((void**)&nmh,    g_nmh);
    cudaGetSymbolAddress((void**)&xh,     g_xh);
    cudaGetSymbolAddress((void**)&h16,    g_h16);
    cudaGetSymbolAddress((void**)&yh,     g_yh);
    cudaGetSymbolAddress((void**)&deg,    g_deg);
    cudaGetSymbolAddress((void**)&scale,  g_scale);
    cudaGetSymbolAddress((void**)&shift,  g_shift);
    cudaGetSymbolAddress((void**)&colsum, g_colsum);
    cudaGetSymbolAddress((void**)&colsq,  g_colsq);
    cudaGetSymbolAddress((void**)&hg,     g_hg);
    cudaGetSymbolAddress((void**)&cnt,    g_cnt);
    cudaGetSymbolAddress((void**)&hgh,    g_hgh);
    cudaGetSymbolAddress((void**)&t1h,    g_t1h);
    cudaGetSymbolAddress((void**)&t2h,    g_t2h);
    cudaGetSymbolAddress((void**)&wh1s,   g_wh1s);
    cudaGetSymbolAddress((void**)&wh1n,   g_wh1n);
    cudaGetSymbolAddress((void**)&wh2s,   g_wh2s);
    cudaGetSymbolAddress((void**)&wh2n,   g_wh2n);
    cudaGetSymbolAddress((void**)&wh3s,   g_wh3s);
    cudaGetSymbolAddress((void**)&wh3n,   g_wh3n);
    cudaGetSymbolAddress((void**)&wfc1,   g_wfc1);
    cudaGetSymbolAddress((void**)&wfc2,   g_wfc2);

    cudaFuncSetAttribute((const void*)tc_gemm<K1,  HID,  true,  false>, cudaFuncAttributeMaxDynamicSharedMemorySize, TCG_SMEM_BYTES);
    cudaFuncSetAttribute((const void*)tc_gemm<HID, HID,  true,  false>, cudaFuncAttributeMaxDynamicSharedMemorySize, TCG_SMEM_BYTES);
    cudaFuncSetAttribute((const void*)tc_gemm<HID, HID,  false, true>,  cudaFuncAttributeMaxDynamicSharedMemorySize, TCG_SMEM_BYTES);
    cudaFuncSetAttribute((const void*)tc_gemm<HID, MIDD, false, true>,  cudaFuncAttributeMaxDynamicSharedMemorySize, TCG_SMEM_BYTES);

    cudaStream_t s = 0;

    // weight transposes (+ fp16 convert), input pad
    dim3 tblk(32, 8);
    transpose_cvt1<<<dim3(HID / 32, K1 / 32), tblk, 0, s>>>(Ws1, wh1s);
    transpose_cvt1<<<dim3(HID / 32, K1 / 32), tblk, 0, s>>>(Wn1, wh1n);
    transpose_cvt_g<<<dim3(HID / 32, HID / 32), tblk, 0, s>>>(Ws2, wh2s, HID, HID);
    transpose_cvt_g<<<dim3(HID / 32, HID / 32), tblk, 0, s>>>(Wn2, wh2n, HID, HID);
    transpose_cvt_g<<<dim3(HID / 32, HID / 32), tblk, 0, s>>>(Ws3, wh3s, HID, HID);
    transpose_cvt_g<<<dim3(HID / 32, HID / 32), tblk, 0, s>>>(Wn3, wh3n, HID, HID);
    transpose_cvt_g<<<dim3(HID / 32, HID / 32), tblk, 0, s>>>(fc1_w, wfc1, HID, HID);
    transpose_cvt_g<<<dim3(MIDD / 32, HID / 32), tblk, 0, s>>>(fc2_w, wfc2, HID, MIDD);
    hpad<<<Nn, K1, 0, s>>>(h, h16);

    // degrees
    cudaMemsetAsync(deg, 0, Nn * sizeof(float), s);
    deg_kernel<<<Ee / 256, 256, 0, s>>>(dst, deg);

    dim3 tc_grid(HID / 128, Nn / 128);
    dim3 ew4_grid(HID / 4 / 256, Nn);

    // ---- Layer 1 (K = 64, tensor GEMM, fused BN stats + deg-fold) ----
    cudaMemsetAsync(nmh, 0, (size_t)Nn * K1 * sizeof(__half), s);
    scatter_add_h2<<<dim3(Ee, 1), 32, 0, s>>>(h16, src, dst, nmh, K1);
    cudaMemsetAsync(colsum, 0, HID * sizeof(float), s);
    cudaMemsetAsync(colsq,  0, HID * sizeof(float), s);
    tc_gemm<K1, HID, true, false><<<tc_grid, 256, TCG_SMEM_BYTES, s>>>(
        nmh, wh1n, h16, wh1s, b1, deg, yh, colsum, colsq);
    bn_scale<<<HID / 256, 256, 0, s>>>(colsum, colsq, g1, be1, scale, shift);
    bn_apply_h<<<ew4_grid, 256, 0, s>>>(yh, xh, scale, shift);

    // ---- Layer 2 ----
    cudaMemsetAsync(nmh, 0, (size_t)Nn * HID * sizeof(__half), s);
    scatter_add_h2<<<dim3(Ee, HID / 2 / 128), 128, 0, s>>>(xh, src, dst, nmh, HID);
    cudaMemsetAsync(colsum, 0, HID * sizeof(float), s);
    cudaMemsetAsync(colsq,  0, HID * sizeof(float), s);
    tc_gemm<HID, HID, true, false><<<tc_grid, 256, TCG_SMEM_BYTES, s>>>(
        nmh, wh2n, xh, wh2s, b2, deg, yh, colsum, colsq);
    bn_scale<<<HID / 256, 256, 0, s>>>(colsum, colsq, g2, be2, scale, shift);
    bn_apply_h<<<ew4_grid, 256, 0, s>>>(yh, xh, scale, shift);

    // ---- Layer 3 ----
    cudaMemsetAsync(nmh, 0, (size_t)Nn * HID * sizeof(__half), s);
    scatter_add_h2<<<dim3(Ee, HID / 2 / 128), 128, 0, s>>>(xh, src, dst, nmh, HID);
    cudaMemsetAsync(colsum, 0, HID * sizeof(float), s);
    cudaMemsetAsync(colsq,  0, HID * sizeof(float), s);
    tc_gemm<HID, HID, true, false><<<tc_grid, 256, TCG_SMEM_BYTES, s>>>(
        nmh, wh3n, xh, wh3s, b3, deg, yh, colsum, colsq);
    bn_scale<<<HID / 256, 256, 0, s>>>(colsum, colsq, g3, be3, scale, shift);

    // ---- Pooling (fused BN apply) ----
    cudaMemsetAsync(hg, 0, Gg * HID * sizeof(float), s);
    cudaMemsetAsync(cnt, 0, Gg * sizeof(float), s);
    cudaMemsetAsync(hgh, 0, 128 * HID * sizeof(__half), s);
    cnt_kernel<<<Nn / 256, 256, 0, s>>>(gid, cnt);
    bn_apply_pool<<<ew4_grid, 256, 0, s>>>(yh, gid, scale, shift, hg);
    hg_div_h<<<dim3(HID / 256, Gg), 256, 0, s>>>(hg, cnt, hgh);

    // ---- MLP head: fc1 and fc2 on tensor path (M padded to 128) ----
    tc_gemm<HID, HID, false, true><<<dim3(HID / 128, 1), 256, TCG_SMEM_BYTES, s>>>(
        nullptr, nullptr, hgh, wfc1, fc1_b, deg, t1h, nullptr, nullptr);
    tc_gemm<HID, MIDD, false, true><<<dim3(MIDD / 128, 1), 256, TCG_SMEM_BYTES, s>>>(
        nullptr, nullptr, t1h, wfc2, fc2_b, deg, t2h, nullptr, nullptr);
    head_gemm_h<<<dim3(1, Gg), 128, MIDD * sizeof(float), s>>>(t2h, fc3_w, fc3_b, out, MIDD, NCLS);
}